// round 2
// baseline (speedup 1.0000x reference)
#include <cuda_runtime.h>
#include <cuda_bf16.h>
#include <math.h>

#define NNODES  50000
#define BATCH   2
#define DH      128
#define TOTROWS (BATCH * NNODES)

// Scratch (device globals: allocation-guard-safe)
__device__ float g_support[(size_t)TOTROWS * DH];
__device__ float g_agg[(size_t)TOTROWS * DH];
__device__ float g_acc[32];

// ---------------------------------------------------------------------------
// Kernel 1: support = x @ W  (fp32, W in smem, 4 rows/thread via transposed
// x staging: one LDS.128 feeds 4 FMAs). Also zeroes g_agg rows and g_acc.
// Block: 256 threads = 2 halves x 128 cols. 8 rows per block-iteration.
// ---------------------------------------------------------------------------
__global__ void k_gemm(const float* __restrict__ x, const float* __restrict__ W) {
    extern __shared__ float sm[];
    float*  Ws = sm;                         // 128*128 floats
    float4* xs = (float4*)(sm + DH * DH);    // 256 float4 (2 halves x 128)

    int tid  = threadIdx.x;
    int half = tid >> 7;      // 0 or 1
    int t    = tid & 127;     // output column

    for (int i = tid; i < DH * DH; i += blockDim.x) Ws[i] = W[i];
    if (blockIdx.x == 0 && tid < 32) g_acc[tid] = 0.f;

    for (int row0 = blockIdx.x * 8; row0 < TOTROWS; row0 += gridDim.x * 8) {
        int r0 = row0 + half * 4;
        float4 v;
        float* vp = (float*)&v;
        #pragma unroll
        for (int rr = 0; rr < 4; rr++) {
            int r = r0 + rr;
            vp[rr] = (r < TOTROWS) ? x[(size_t)r * DH + t] : 0.f;
        }
        __syncthreads();                 // prior iter's xs reads done (covers Ws on iter 0)
        xs[half * DH + t] = v;
        __syncthreads();

        float a0 = 0.f, a1 = 0.f, a2 = 0.f, a3 = 0.f;
        const float4* xh = xs + half * DH;
        #pragma unroll 8
        for (int d = 0; d < DH; d++) {
            float  w  = Ws[d * DH + t];
            float4 xv = xh[d];
            a0 = fmaf(xv.x, w, a0);
            a1 = fmaf(xv.y, w, a1);
            a2 = fmaf(xv.z, w, a2);
            a3 = fmaf(xv.w, w, a3);
        }
        float res[4] = {a0, a1, a2, a3};
        #pragma unroll
        for (int rr = 0; rr < 4; rr++) {
            int r = r0 + rr;
            if (r < TOTROWS) {
                size_t off = (size_t)r * DH + t;
                g_support[off] = res[rr];
                g_agg[off]     = 0.f;
            }
        }
    }
}

// ---------------------------------------------------------------------------
// Kernel 2: scatter-add. One warp per edge, both batches. Vectorized
// red.global.add.v4.f32 (sm_90+) => 1 RED.128 per lane per batch.
// ---------------------------------------------------------------------------
__device__ __forceinline__ void red_add_v4(float4* addr, float4 v) {
    asm volatile("red.global.add.v4.f32 [%0], {%1, %2, %3, %4};"
                 :: "l"(addr), "f"(v.x), "f"(v.y), "f"(v.z), "f"(v.w)
                 : "memory");
}

__global__ void k_scatter(const int* __restrict__ ei, int nedges) {
    int gw   = (int)((blockIdx.x * (size_t)blockDim.x + threadIdx.x) >> 5);
    int lane = threadIdx.x & 31;
    if (gw >= nedges) return;

    int src = __ldg(ei + gw);
    int dst = __ldg(ei + nedges + gw);

    const float4* s0 = (const float4*)g_support + (size_t)src * 32;
    float4*       a0 = (float4*)g_agg          + (size_t)dst * 32;

    float4 v0 = s0[lane];
    red_add_v4(a0 + lane, v0);

    const float4* s1 = s0 + (size_t)NNODES * 32;
    float4*       a1 = a0 + (size_t)NNODES * 32;
    float4 v1 = s1[lane];
    red_add_v4(a1 + lane, v1);
}

// ---------------------------------------------------------------------------
// Kernel 3: per-node MLP (gelu -> 128x64 relu -> 64x32 relu -> 32x10) with
// mean-reduction. One warp per (batch,node) row; weights in smem; per-warp
// register accumulators; block-level reduce -> 20 global atomics per block.
// ---------------------------------------------------------------------------
__device__ __forceinline__ float gelu_exact(float v) {
    return 0.5f * v * (1.0f + erff(v * 0.70710678118654752f));
}

__global__ void k_mlp(const float* __restrict__ b,
                      const float* __restrict__ W1, const float* __restrict__ b1,
                      const float* __restrict__ W2, const float* __restrict__ b2,
                      const float* __restrict__ W3, const float* __restrict__ b3) {
    extern __shared__ float sm[];
    float* W1s  = sm;             // 128*64 = 8192
    float* W2s  = W1s + 8192;     // 64*32  = 2048
    float* W3s  = W2s + 2048;     // 32*10  = 320
    float* bs   = W3s + 320;      // 128
    float* b1s  = bs  + 128;      // 64
    float* b2s  = b1s + 64;       // 32
    float* b3s  = b2s + 32;       // 16 (pad)
    float* accs = b3s + 16;       // 32 (pad)
    float* bufs = accs + 32;      // 8 warps * 224 (h:128, h1:64, h2:32)

    int tid = threadIdx.x;
    for (int i = tid; i < 8192; i += blockDim.x) W1s[i] = W1[i];
    for (int i = tid; i < 2048; i += blockDim.x) W2s[i] = W2[i];
    for (int i = tid; i < 320;  i += blockDim.x) W3s[i] = W3[i];
    if (tid < 128) bs[tid]  = b[tid];
    if (tid < 64)  b1s[tid] = b1[tid];
    if (tid < 32)  b2s[tid] = b2[tid];
    if (tid < 16)  b3s[tid] = (tid < 10) ? b3[tid] : 0.f;
    if (tid < 32)  accs[tid] = 0.f;
    __syncthreads();

    int w    = tid >> 5;
    int lane = tid & 31;
    float* hb  = bufs + w * 224;
    float* h1b = hb + 128;
    float* h2b = h1b + 64;

    int nwarps = (int)((gridDim.x * (size_t)blockDim.x) >> 5);
    int gw     = (int)((blockIdx.x * (size_t)blockDim.x + tid) >> 5);

    float4 bb  = ((const float4*)bs)[lane];
    float2 b1v = ((const float2*)b1s)[lane];
    float  b2a = b2s[lane];
    float  b3a = (lane < 10) ? b3s[lane] : 0.f;

    float accB0 = 0.f, accB1 = 0.f;

    for (int row = gw; row < TOTROWS; row += nwarps) {
        // h = gelu(agg + b)
        float4 a = ((const float4*)g_agg)[(size_t)row * 32 + lane];
        a.x = gelu_exact(a.x + bb.x);
        a.y = gelu_exact(a.y + bb.y);
        a.z = gelu_exact(a.z + bb.z);
        a.w = gelu_exact(a.w + bb.w);
        ((float4*)hb)[lane] = a;
        __syncwarp();

        // h1 = relu(h @ W1 + b1): lane computes outputs 2*lane, 2*lane+1
        float2 s = b1v;
        const float4* hb4 = (const float4*)hb;
        const float2* w1p = (const float2*)W1s + lane;   // row j: + j*32
        #pragma unroll 8
        for (int j4 = 0; j4 < 32; j4++) {
            float4 h4 = hb4[j4];
            float2 w0 = w1p[(j4 * 4 + 0) * 32];
            float2 w1 = w1p[(j4 * 4 + 1) * 32];
            float2 w2 = w1p[(j4 * 4 + 2) * 32];
            float2 w3 = w1p[(j4 * 4 + 3) * 32];
            s.x = fmaf(h4.x, w0.x, s.x); s.y = fmaf(h4.x, w0.y, s.y);
            s.x = fmaf(h4.y, w1.x, s.x); s.y = fmaf(h4.y, w1.y, s.y);
            s.x = fmaf(h4.z, w2.x, s.x); s.y = fmaf(h4.z, w2.y, s.y);
            s.x = fmaf(h4.w, w3.x, s.x); s.y = fmaf(h4.w, w3.y, s.y);
        }
        s.x = fmaxf(s.x, 0.f);
        s.y = fmaxf(s.y, 0.f);
        ((float2*)h1b)[lane] = s;
        __syncwarp();

        // h2 = relu(h1 @ W2 + b2): lane computes output `lane` (of 32)
        float s3 = b2a;
        const float4* h1b4 = (const float4*)h1b;
        #pragma unroll 4
        for (int j4 = 0; j4 < 16; j4++) {
            float4 h4 = h1b4[j4];
            s3 = fmaf(h4.x, W2s[(j4 * 4 + 0) * 32 + lane], s3);
            s3 = fmaf(h4.y, W2s[(j4 * 4 + 1) * 32 + lane], s3);
            s3 = fmaf(h4.z, W2s[(j4 * 4 + 2) * 32 + lane], s3);
            s3 = fmaf(h4.w, W2s[(j4 * 4 + 3) * 32 + lane], s3);
        }
        h2b[lane] = fmaxf(s3, 0.f);
        __syncwarp();

        // h3 = h2 @ W3 + b3: lanes 0..9 each produce one output, accumulate
        if (lane < 10) {
            float s4 = b3a;
            #pragma unroll
            for (int j = 0; j < 32; j++)
                s4 = fmaf(h2b[j], W3s[j * 10 + lane], s4);
            if (row < NNODES) accB0 += s4; else accB1 += s4;
        }
        __syncwarp();
    }

    // block-level reduce, then 20 global atomics per block
    if (lane < 10) {
        atomicAdd(&accs[lane],      accB0);
        atomicAdd(&accs[10 + lane], accB1);
    }
    __syncthreads();
    if (tid < 20) atomicAdd(&g_acc[tid], accs[tid]);
}

// ---------------------------------------------------------------------------
// Kernel 4: finalize mean -> d_out (2,10)
// ---------------------------------------------------------------------------
__global__ void k_fin(float* __restrict__ out) {
    int t = threadIdx.x;
    if (t < 20) out[t] = g_acc[t] * (1.0f / (float)NNODES);
}

extern "C" void kernel_launch(void* const* d_in, const int* in_sizes, int n_in,
                              void* d_out, int out_size) {
    const float* x  = (const float*)d_in[0];
    const int*   ei = (const int*)  d_in[1];
    const float* W  = (const float*)d_in[2];
    const float* b  = (const float*)d_in[3];
    const float* W1 = (const float*)d_in[4];
    const float* b1 = (const float*)d_in[5];
    const float* W2 = (const float*)d_in[6];
    const float* b2 = (const float*)d_in[7];
    const float* W3 = (const float*)d_in[8];
    const float* b3 = (const float*)d_in[9];
    float* out = (float*)d_out;

    int nedges = in_sizes[1] / 2;

    const int GEMM_SMEM = (DH * DH + 2 * DH * 4) * (int)sizeof(float);  // 69632
    const int MLP_SMEM  = (8192 + 2048 + 320 + 128 + 64 + 32 + 16 + 32 + 8 * 224)
                          * (int)sizeof(float);                          // 50496

    cudaFuncSetAttribute(k_gemm, cudaFuncAttributeMaxDynamicSharedMemorySize, GEMM_SMEM);
    cudaFuncSetAttribute(k_mlp,  cudaFuncAttributeMaxDynamicSharedMemorySize, MLP_SMEM);

    // 1. support = x@W, zero agg + acc
    k_gemm<<<1250, 256, GEMM_SMEM>>>(x, W);

    // 2. scatter-add: one warp per edge
    int sc_blocks = (nedges * 32 + 255) / 256;
    k_scatter<<<sc_blocks, 256>>>(ei, nedges);

    // 3. MLP + mean reduce
    k_mlp<<<2048, 256, MLP_SMEM>>>(b, W1, b1, W2, b2, W3, b3);

    // 4. finalize
    k_fin<<<1, 32>>>(out);
}